// round 5
// baseline (speedup 1.0000x reference)
#include <cuda_runtime.h>
#include <cuda_bf16.h>

// ---------------------------------------------------------------------------
// BEVSampling: 3 kernels
//  K0: transpose 4-level features NCHW -> NHWC scratch (g_feat)
//  K1: pos-MLP (fp32 GEMM-in-smem)  -> writes pos directly into d_out
//  K2: project + multi-level bilinear sample, += into d_out (coalesced via smem)
// ---------------------------------------------------------------------------

#define NUM_CAMS 6
#define EMBED    128
#define NP       8          // pillar points
#define GQ       10000      // 100x100 queries
#define NPTS     (GQ * NP)  // 80000

#define FEAT_TOTAL 2872320  // 6*128*(2816+704+176+44)

__device__ float g_feat[FEAT_TOTAL]; // ~11.5 MB NHWC scratch

// ---------------------------------------------------------------------------
// K0: NCHW -> NHWC transpose. Output index enumerates g_feat layout directly,
// so writes are perfectly coalesced; reads are channel-strided but the whole
// tensor is L2-resident (11.5MB), one-shot cost.
// ---------------------------------------------------------------------------
__global__ __launch_bounds__(256) void k_transpose(
    const float* __restrict__ f0, const float* __restrict__ f1,
    const float* __restrict__ f2, const float* __restrict__ f3)
{
    int idx = blockIdx.x * 256 + threadIdx.x;
    if (idx >= FEAT_TOTAL) return;

    const float* src;
    int rel, HW;
    if (idx < 2162688)      { src = f0; rel = idx;            HW = 2816; }
    else if (idx < 2703360) { src = f1; rel = idx - 2162688;  HW = 704;  }
    else if (idx < 2838528) { src = f2; rel = idx - 2703360;  HW = 176;  }
    else                    { src = f3; rel = idx - 2838528;  HW = 44;   }

    int hw128 = HW << 7;
    int cam = rel / hw128;
    int r2  = rel - cam * hw128;
    int pix = r2 >> 7;
    int c   = r2 & 127;
    g_feat[idx] = src[(cam * EMBED + c) * HW + pix];
}

// ---------------------------------------------------------------------------
// K1: pos = relu(ref @ w1 + b1) @ w2 + b2, written to d_out[c][p][q].
// Block: 512 threads, persistent over batches of 64 q (fixed p).
// w2 (128KB) staged once per block in dynamic smem; hidden H[256][64] in smem.
// Thread (qi = t&63, cg = t>>6) owns 16 output channels for one q.
// Output transposed through smem for coalesced 128B stores.
// ---------------------------------------------------------------------------
#define K1_THREADS 512
#define K1_QB      64
#define K1_NBATCH  157            /* ceil(10000/64) */
#define K1_TOTB    (K1_NBATCH * NP)
// smem floats: w2(32768) w1(768) b1(256) b2(128) H(16384) refc(192)
#define K1_SMEM_FLOATS (32768 + 768 + 256 + 128 + 16384 + 192)
#define K1_SMEM_BYTES  (K1_SMEM_FLOATS * 4)

__global__ __launch_bounds__(K1_THREADS) void k_mlp(
    const float* __restrict__ ref,   // [8,100,100,3] == [p, q, 3]
    const float* __restrict__ w1,    // [3,256]
    const float* __restrict__ b1,    // [256]
    const float* __restrict__ w2,    // [256,128]
    const float* __restrict__ b2,    // [128]
    float* __restrict__ out)         // [128, 8, 10000]
{
    extern __shared__ float sm[];
    float* w2s  = sm;            // 32768
    float* w1s  = w2s + 32768;   // 768
    float* b1s  = w1s + 768;     // 256
    float* b2s  = b1s + 256;     // 128
    float* Hs   = b2s + 128;     // 16384  (reused as S[128][65] for output)
    float* refc = Hs + 16384;    // 192

    const int t = threadIdx.x;

    for (int i = t; i < 32768; i += K1_THREADS) w2s[i] = w2[i];
    for (int i = t; i < 768;   i += K1_THREADS) w1s[i] = w1[i];
    if (t < 256) b1s[t] = b1[t];
    if (t < 128) b2s[t] = b2[t];
    __syncthreads();

    const int qi = t & 63;
    const int cg = t >> 6;       // 0..7
    const int c0 = cg * 16;

    for (int batch = blockIdx.x; batch < K1_TOTB; batch += gridDim.x) {
        const int p  = batch / K1_NBATCH;
        const int q0 = (batch - p * K1_NBATCH) * K1_QB;

        // stage 0: load normalized ref coords for this q-batch
        if (t < 192) {
            int qq = t & 63, d = t >> 6;
            int q = q0 + qq;
            refc[(d << 6) + qq] = (q < GQ) ? ref[(p * GQ + q) * 3 + d] : 0.f;
        }
        __syncthreads();

        // stage 1: hidden H[k][qi] = relu(x*w1_0k + y*w1_1k + z*w1_2k + b1_k)
        {
            float rx = refc[qi], ry = refc[64 + qi], rz = refc[128 + qi];
            int kg = cg; // 8 k-groups of 32
            #pragma unroll 4
            for (int j = 0; j < 32; ++j) {
                int k = kg * 32 + j;
                float h = fmaf(rx, w1s[k],
                          fmaf(ry, w1s[256 + k],
                          fmaf(rz, w1s[512 + k], b1s[k])));
                Hs[(k << 6) + qi] = fmaxf(h, 0.f);
            }
        }
        __syncthreads();

        // stage 2: out_c = b2_c + sum_k h_k * w2[k][c], 16 channels/thread
        float acc[16];
        #pragma unroll
        for (int j = 0; j < 16; ++j) acc[j] = b2s[c0 + j];

        #pragma unroll 2
        for (int k = 0; k < 256; ++k) {
            float h = Hs[(k << 6) + qi];
            const float4* wr = reinterpret_cast<const float4*>(w2s + (k << 7) + c0);
            float4 a = wr[0], b = wr[1], c4 = wr[2], d4 = wr[3];
            acc[0]  = fmaf(h, a.x,  acc[0]);  acc[1]  = fmaf(h, a.y,  acc[1]);
            acc[2]  = fmaf(h, a.z,  acc[2]);  acc[3]  = fmaf(h, a.w,  acc[3]);
            acc[4]  = fmaf(h, b.x,  acc[4]);  acc[5]  = fmaf(h, b.y,  acc[5]);
            acc[6]  = fmaf(h, b.z,  acc[6]);  acc[7]  = fmaf(h, b.w,  acc[7]);
            acc[8]  = fmaf(h, c4.x, acc[8]);  acc[9]  = fmaf(h, c4.y, acc[9]);
            acc[10] = fmaf(h, c4.z, acc[10]); acc[11] = fmaf(h, c4.w, acc[11]);
            acc[12] = fmaf(h, d4.x, acc[12]); acc[13] = fmaf(h, d4.y, acc[13]);
            acc[14] = fmaf(h, d4.z, acc[14]); acc[15] = fmaf(h, d4.w, acc[15]);
        }
        __syncthreads(); // everyone done reading Hs before we reuse it as S

        // stage 3: transpose through smem (S[c][qi], stride 65) for coalesced stores
        float* S = Hs;
        #pragma unroll
        for (int j = 0; j < 16; ++j) S[(c0 + j) * 65 + qi] = acc[j];
        __syncthreads();

        for (int e = t; e < EMBED * K1_QB; e += K1_THREADS) {
            int cc = e >> 6, qq = e & 63;
            int q = q0 + qq;
            if (q < GQ) out[(cc * NP + p) * GQ + q] = S[cc * 65 + qq];
        }
        __syncthreads();
    }
}

// ---------------------------------------------------------------------------
// K2: projection + multi-level bilinear sampling.
// Block: 256 threads = two 128-thread channel groups, each processing one q
// at a time (32 q per block, fixed p). Taps read 512B contiguous from NHWC
// g_feat. Results transposed through smem; coalesced += into d_out.
// ---------------------------------------------------------------------------
__global__ __launch_bounds__(256) void k_sample(
    const float* __restrict__ ref,   // [8, 10000, 3] normalized
    const float* __restrict__ l2i,   // [6,4,4]
    float* __restrict__ out)         // [128, 8, 10000]
{
    // level tables as device-local consts (folded to immediates after unroll)
    const int LW_[4]   = {88, 44, 22, 11};
    const int LH_[4]   = {32, 16, 8, 4};
    const int LHW_[4]  = {2816, 704, 176, 44};
    const int LOFF_[4] = {0, 2162688, 2703360, 2838528};

    __shared__ float refc[96];          // [3][32]
    __shared__ float l2is[96];
    __shared__ float um[NUM_CAMS * 32];
    __shared__ float vm[NUM_CAMS * 32];
    __shared__ int   vld[NUM_CAMS * 32];
    __shared__ float S[EMBED * 33];     // [c][qi], pad 33

    const int t  = threadIdx.x;
    const int p  = blockIdx.y;
    const int q0 = blockIdx.x * 32;

    if (t < 96) {
        l2is[t] = l2i[t];
        int qi = t & 31, d = t >> 5;
        int q = q0 + qi;
        refc[(d << 5) + qi] = (q < GQ) ? ref[(p * GQ + q) * 3 + d] : 0.f;
    }
    __syncthreads();

    if (t < 192) {
        int qi = t & 31, cam = t >> 5;
        float rx = refc[qi], ry = refc[32 + qi], rz = refc[64 + qi];
        // denormalize to metric pc_range
        float px = fmaf(rx, 100.f, -50.f);
        float py = fmaf(ry, 100.f, -50.f);
        float pz = fmaf(rz,   8.f,  -4.f);
        const float* M = &l2is[cam * 16];
        float cx = fmaf(M[0], px, fmaf(M[1],  py, fmaf(M[2],  pz, M[3])));
        float cy = fmaf(M[4], px, fmaf(M[5],  py, fmaf(M[6],  pz, M[7])));
        float cz = fmaf(M[8], px, fmaf(M[9],  py, fmaf(M[10], pz, M[11])));
        float zs = fmaxf(cz, 1e-6f);
        float u = __fdiv_rn(__fdiv_rn(cx, zs), 704.f);
        float v = __fdiv_rn(__fdiv_rn(cy, zs), 256.f);
        um[cam * 32 + qi] = u;
        vm[cam * 32 + qi] = v;
        vld[cam * 32 + qi] = (cz > 1e-6f) & (u > 0.f) & (u < 1.f)
                           & (v > 0.f) & (v < 1.f);
    }
    __syncthreads();

    const int c    = t & 127;
    const int half = t >> 7;

    for (int it = 0; it < 16; ++it) {
        int qi = it * 2 + half;
        float acc = 0.f;
        #pragma unroll
        for (int cam = 0; cam < NUM_CAMS; ++cam) {
            if (!vld[cam * 32 + qi]) continue;   // uniform across the 128-thread group
            float u = um[cam * 32 + qi];
            float v = vm[cam * 32 + qi];
            #pragma unroll
            for (int l = 0; l < 4; ++l) {
                const int W = LW_[l], H = LH_[l];
                float x = fmaf(u, (float)W, -0.5f);
                float y = fmaf(v, (float)H, -0.5f);
                float xf = floorf(x), yf = floorf(y);
                float wx = x - xf,   wy = y - yf;
                int x0 = (int)xf, y0 = (int)yf;
                const float* fb = g_feat + LOFF_[l] + cam * (LHW_[l] << 7);
                bool xa = (x0 >= 0)  & (x0 < W);
                bool xb = (x0 >= -1) & (x0 < W - 1);
                bool ya = (y0 >= 0)  & (y0 < H);
                bool yb = (y0 >= -1) & (y0 < H - 1);
                float v00 = 0.f, v01 = 0.f, v10 = 0.f, v11 = 0.f;
                int base = (y0 * W + x0) << 7;
                if (xa & ya) v00 = fb[base + c];
                if (xb & ya) v01 = fb[base + 128 + c];
                if (xa & yb) v10 = fb[base + (W << 7) + c];
                if (xb & yb) v11 = fb[base + (W << 7) + 128 + c];
                float top = fmaf(v01 - v00, wx, v00);
                float bot = fmaf(v11 - v10, wx, v10);
                acc += fmaf(bot - top, wy, top);
            }
        }
        S[c * 33 + qi] = acc * 0.25f;  // mean over 4 levels
    }
    __syncthreads();

    // coalesced RMW: out += sampled  (pos already written by k_mlp)
    for (int e = t; e < EMBED * 32; e += 256) {
        int cc = e >> 5, qi = e & 31;
        int q = q0 + qi;
        if (q < GQ) {
            int oi = (cc * NP + p) * GQ + q;
            out[oi] += S[cc * 33 + qi];
        }
    }
}

// ---------------------------------------------------------------------------
extern "C" void kernel_launch(void* const* d_in, const int* in_sizes, int n_in,
                              void* d_out, int out_size)
{
    const float* f0  = (const float*)d_in[0];
    const float* f1  = (const float*)d_in[1];
    const float* f2  = (const float*)d_in[2];
    const float* f3  = (const float*)d_in[3];
    const float* ref = (const float*)d_in[4];
    const float* l2i = (const float*)d_in[5];
    const float* w1  = (const float*)d_in[6];
    const float* b1  = (const float*)d_in[7];
    const float* w2  = (const float*)d_in[8];
    const float* b2  = (const float*)d_in[9];
    float* out = (float*)d_out;

    // K0: feature transpose to NHWC scratch
    k_transpose<<<(FEAT_TOTAL + 255) / 256, 256>>>(f0, f1, f2, f3);

    // K1: pos MLP -> d_out
    cudaFuncSetAttribute(k_mlp, cudaFuncAttributeMaxDynamicSharedMemorySize,
                         K1_SMEM_BYTES);
    k_mlp<<<148, K1_THREADS, K1_SMEM_BYTES>>>(ref, w1, b1, w2, b2, out);

    // K2: sampling, += into d_out
    dim3 grid((GQ + 31) / 32, NP);
    k_sample<<<grid, 256>>>(ref, l2i, out);
}

// round 7
// speedup vs baseline: 1.8538x; 1.8538x over previous
#include <cuda_runtime.h>
#include <cuda_bf16.h>
#include <cstdint>

// ---------------------------------------------------------------------------
// BEVSampling (sm_100 baseline PTX — no tcgen05 on this target):
//  k_prep:      w2 fp32 -> split bf16 hi/lo, transposed to [n][k] in gmem
//  k_transpose: NCHW -> NHWC features (tiled, coalesced both sides)
//  k_mlp_mma:   pos-MLP as mma.sync bf16 split GEMM -> writes pos into d_out
//  k_sample:    project + multi-level bilinear sample, += into d_out
// ---------------------------------------------------------------------------

#define NUM_CAMS 6
#define EMBED    128
#define NP       8
#define GQ       10000
#define NPTS     80000
#define FEAT_TOTAL 2872320  // 6*128*(2816+704+176+44)

__device__ float g_feat[FEAT_TOTAL];          // ~11.5 MB NHWC scratch
__device__ __nv_bfloat16 g_w2h[256 * 128];    // w2^T hi, [n][k]
__device__ __nv_bfloat16 g_w2l[256 * 128];    // w2^T lo, [n][k]

// ---------------------------------------------------------------------------
// k_prep: split w2 into bf16 hi/lo, store transposed [n][k] (k contiguous).
// ---------------------------------------------------------------------------
__global__ __launch_bounds__(256) void k_prep(const float* __restrict__ w2)
{
    int i = blockIdx.x * 256 + threadIdx.x;   // 32768 elements
    if (i >= 32768) return;
    int n = i >> 8, k = i & 255;
    float v = w2[k * 128 + n];
    __nv_bfloat16 h = __float2bfloat16(v);
    __nv_bfloat16 l = __float2bfloat16(v - __bfloat162float(h));
    g_w2h[n * 256 + k] = h;
    g_w2l[n * 256 + k] = l;
}

// ---------------------------------------------------------------------------
// k_transpose: tiled NCHW -> NHWC. Block (32,8), 32x32 tiles.
// grid.x = (88 + 22 + 6 + 2)*4*6 = 2832
// ---------------------------------------------------------------------------
__global__ __launch_bounds__(256) void k_transpose(
    const float* __restrict__ f0, const float* __restrict__ f1,
    const float* __restrict__ f2, const float* __restrict__ f3)
{
    __shared__ float s[32 * 33];
    int bid = blockIdx.x;
    const float* src; int HW, ptiles, loff, tl;
    if (bid < 2112)      { src = f0; HW = 2816; ptiles = 88; loff = 0;       tl = bid; }
    else if (bid < 2640) { src = f1; HW = 704;  ptiles = 22; loff = 2162688; tl = bid - 2112; }
    else if (bid < 2784) { src = f2; HW = 176;  ptiles = 6;  loff = 2703360; tl = bid - 2640; }
    else                 { src = f3; HW = 44;   ptiles = 2;  loff = 2838528; tl = bid - 2784; }

    int per_cam = ptiles * 4;
    int cam = tl / per_cam;
    int r   = tl - cam * per_cam;
    int c0  = (r & 3) * 32;
    int p0  = (r >> 2) * 32;
    int tx = threadIdx.x, ty = threadIdx.y;

    const float* sp = src + (long)cam * 128 * HW;
    #pragma unroll
    for (int j = 0; j < 4; ++j) {
        int cl = ty + j * 8;
        int p  = p0 + tx;
        float v = (p < HW) ? sp[(c0 + cl) * HW + p] : 0.f;
        s[tx * 33 + cl] = v;
    }
    __syncthreads();
    float* dst = g_feat + loff + (long)cam * HW * 128;
    #pragma unroll
    for (int j = 0; j < 4; ++j) {
        int pl = ty + j * 8;
        int p  = p0 + pl;
        if (p < HW) dst[p * 128 + c0 + tx] = s[pl * 33 + tx];
    }
}

// ---------------------------------------------------------------------------
// mma.sync bf16 helper (sm_80+ baseline, valid on sm_100 non-'a')
// ---------------------------------------------------------------------------
__device__ __forceinline__ void mma_bf16(float* d,
    uint32_t a0, uint32_t a1, uint32_t a2, uint32_t a3,
    uint32_t b0, uint32_t b1)
{
    asm volatile(
        "mma.sync.aligned.m16n8k16.row.col.f32.bf16.bf16.f32 "
        "{%0,%1,%2,%3}, {%4,%5,%6,%7}, {%8,%9}, {%0,%1,%2,%3};"
        : "+f"(d[0]), "+f"(d[1]), "+f"(d[2]), "+f"(d[3])
        : "r"(a0), "r"(a1), "r"(a2), "r"(a3), "r"(b0), "r"(b1));
}

// ---------------------------------------------------------------------------
// K1: out[c*80000 + n] = (relu(ref@w1 + b1) @ w2)[n][c] + b2[c]
// M=80000 (625 tiles of 128), N=128, K=256 (2 chunks of 128).
// Persistent 148 CTAs x 256 thr. 4x2 warp grid, warp tile 32(M)x64(N).
// smem (bytes):
//   b2s 0..512 | b1s 512..1536 | w1s 1536..4608 | refs 4608..6144
//   Ah 6144 (128x136 bf16 = 34816) | Al 40960 (34816)
//   Bh 75776 (128x264 bf16 = 67584) | Bl 143360 (67584)   total 210944
//   S (epilogue, 128x132 f32 = 67584) aliases Ah/Al.
// ---------------------------------------------------------------------------
#define K1_TILES 625
#define SA 136   /* A k-stride (bf16) : 68 words, 68%32=4 -> conflict-free frags */
#define SB 264   /* B k-stride (bf16) : 132 words, 132%32=4 -> conflict-free */
#define SM_B2   0
#define SM_B1   512
#define SM_W1   1536
#define SM_REF  4608
#define SM_A    6144
#define SM_AL   40960
#define SM_B    75776
#define SM_BL   143360
#define K1_SMEM 210944

__global__ __launch_bounds__(256) void k_mlp_mma(
    const float* __restrict__ ref,   // [80000, 3]
    const float* __restrict__ w1,    // [3,256]
    const float* __restrict__ b1,    // [256]
    const float* __restrict__ b2,    // [128]
    float* __restrict__ out)         // [128, 80000]
{
    extern __shared__ char smb[];
    float* b2s  = (float*)(smb + SM_B2);
    float* b1s  = (float*)(smb + SM_B1);
    float* w1s  = (float*)(smb + SM_W1);
    float* refs = (float*)(smb + SM_REF);
    __nv_bfloat16* Ah = (__nv_bfloat16*)(smb + SM_A);
    __nv_bfloat16* Al = (__nv_bfloat16*)(smb + SM_AL);
    __nv_bfloat16* Bh = (__nv_bfloat16*)(smb + SM_B);
    __nv_bfloat16* Bl = (__nv_bfloat16*)(smb + SM_BL);
    float* S = (float*)(smb + SM_A);  // epilogue alias [c][132]

    const int t    = threadIdx.x;
    const int wid  = t >> 5;
    const int lane = t & 31;
    const int mw   = wid >> 1;          // 0..3  -> m0 = mw*32
    const int nw   = (wid & 1) * 64;    // 0/64

    // one-time staging: params + B (pure copy of pre-split w2)
    for (int i = t; i < 768; i += 256) w1s[i] = w1[i];
    if (t < 256) b1s[t] = b1[t];
    if (t < 128) b2s[t] = b2[t];
    for (int i = t; i < 128 * 32; i += 256) {        // 32 uint4 per n-row
        int n = i >> 5, j = i & 31;
        const uint4* sh = (const uint4*)(g_w2h + n * 256);
        const uint4* sl = (const uint4*)(g_w2l + n * 256);
        *(uint4*)(Bh + n * SB + j * 8) = sh[j];
        *(uint4*)(Bl + n * SB + j * 8) = sl[j];
    }

    for (int tile = blockIdx.x; tile < K1_TILES; tile += 148) {
        const int n0 = tile * 128;

        __syncthreads();  // prior tile's S reads done; B staged (first iter)
        for (int i = t; i < 384; i += 256) {
            int d = i >> 7, r = i & 127;
            refs[d * 128 + r] = ref[(n0 + r) * 3 + d];
        }

        float acc[2][8][4];
        #pragma unroll
        for (int mt = 0; mt < 2; ++mt)
            #pragma unroll
            for (int nt = 0; nt < 8; ++nt)
                #pragma unroll
                for (int j = 0; j < 4; ++j) acc[mt][nt][j] = 0.f;

        for (int chunk = 0; chunk < 2; ++chunk) {
            const int kb = chunk * 128;
            __syncthreads();  // refs ready / prior chunk's frag reads done

            // build A chunk [128 rows][128 k] split hi/lo
            for (int i = t; i < 128 * 64; i += 256) {
                int row = i >> 6, kp = i & 63;
                int k = kb + kp * 2;
                float x = refs[row], y = refs[128 + row], z = refs[256 + row];
                float h0 = fmaxf(fmaf(x, w1s[k],
                                 fmaf(y, w1s[256 + k],
                                 fmaf(z, w1s[512 + k], b1s[k]))), 0.f);
                float h1 = fmaxf(fmaf(x, w1s[k + 1],
                                 fmaf(y, w1s[256 + k + 1],
                                 fmaf(z, w1s[512 + k + 1], b1s[k + 1]))), 0.f);
                __nv_bfloat16 a0 = __float2bfloat16(h0);
                __nv_bfloat16 a1 = __float2bfloat16(h1);
                __nv_bfloat16 e0 = __float2bfloat16(h0 - __bfloat162float(a0));
                __nv_bfloat16 e1 = __float2bfloat16(h1 - __bfloat162float(a1));
                int idx = row * SA + kp * 2;
                *(__nv_bfloat162*)(Ah + idx) = __halves2bfloat162(a0, a1);
                *(__nv_bfloat162*)(Al + idx) = __halves2bfloat162(e0, e1);
            }
            __syncthreads();

            #pragma unroll
            for (int ks = 0; ks < 8; ++ks) {
                const int k0 = ks * 16;        // within chunk (A)
                const int kg = kb + k0;        // global k (B)
                // A fragments for 2 m-tiles, hi and lo
                uint32_t ah[2][4], al[2][4];
                #pragma unroll
                for (int mt = 0; mt < 2; ++mt) {
                    int rbase = (mw * 32 + mt * 16 + (lane >> 2)) * SA
                              + k0 + (lane & 3) * 2;
                    ah[mt][0] = *(const uint32_t*)(Ah + rbase);
                    ah[mt][1] = *(const uint32_t*)(Ah + rbase + 8 * SA);
                    ah[mt][2] = *(const uint32_t*)(Ah + rbase + 8);
                    ah[mt][3] = *(const uint32_t*)(Ah + rbase + 8 * SA + 8);
                    al[mt][0] = *(const uint32_t*)(Al + rbase);
                    al[mt][1] = *(const uint32_t*)(Al + rbase + 8 * SA);
                    al[mt][2] = *(const uint32_t*)(Al + rbase + 8);
                    al[mt][3] = *(const uint32_t*)(Al + rbase + 8 * SA + 8);
                }
                #pragma unroll
                for (int nt = 0; nt < 8; ++nt) {
                    int bbase = (nw + nt * 8 + (lane >> 2)) * SB
                              + kg + (lane & 3) * 2;
                    uint32_t bh0 = *(const uint32_t*)(Bh + bbase);
                    uint32_t bh1 = *(const uint32_t*)(Bh + bbase + 8);
                    uint32_t bl0 = *(const uint32_t*)(Bl + bbase);
                    uint32_t bl1 = *(const uint32_t*)(Bl + bbase + 8);
                    #pragma unroll
                    for (int mt = 0; mt < 2; ++mt) {
                        mma_bf16(acc[mt][nt], ah[mt][0], ah[mt][1], ah[mt][2], ah[mt][3], bh0, bh1);
                        mma_bf16(acc[mt][nt], al[mt][0], al[mt][1], al[mt][2], al[mt][3], bh0, bh1);
                        mma_bf16(acc[mt][nt], ah[mt][0], ah[mt][1], ah[mt][2], ah[mt][3], bl0, bl1);
                    }
                }
            }
        }
        __syncthreads();  // all frag reads done before S aliases A

        // epilogue: D -> S[c][m] (conflict-free), then coalesced store
        #pragma unroll
        for (int mt = 0; mt < 2; ++mt) {
            #pragma unroll
            for (int nt = 0; nt < 8; ++nt) {
                int r = mw * 32 + mt * 16 + (lane >> 2);
                int c = nw + nt * 8 + (lane & 3) * 2;
                S[c * 132 + r]           = acc[mt][nt][0];
                S[(c + 1) * 132 + r]     = acc[mt][nt][1];
                S[c * 132 + r + 8]       = acc[mt][nt][2];
                S[(c + 1) * 132 + r + 8] = acc[mt][nt][3];
            }
        }
        __syncthreads();
        for (int i = t; i < 128 * 128; i += 256) {
            int c = i >> 7, m = i & 127;
            out[c * NPTS + n0 + m] = S[c * 132 + m] + b2s[c];
        }
    }
}

// ---------------------------------------------------------------------------
// K2: projection + multi-level bilinear sampling (unchanged from passing R4).
// ---------------------------------------------------------------------------
__global__ __launch_bounds__(256) void k_sample(
    const float* __restrict__ ref,   // [8, 10000, 3] normalized
    const float* __restrict__ l2i,   // [6,4,4]
    float* __restrict__ out)         // [128, 8, 10000]
{
    const int LW_[4]   = {88, 44, 22, 11};
    const int LH_[4]   = {32, 16, 8, 4};
    const int LHW_[4]  = {2816, 704, 176, 44};
    const int LOFF_[4] = {0, 2162688, 2703360, 2838528};

    __shared__ float refc[96];
    __shared__ float l2is[96];
    __shared__ float um[NUM_CAMS * 32];
    __shared__ float vm[NUM_CAMS * 32];
    __shared__ int   vld[NUM_CAMS * 32];
    __shared__ float S[EMBED * 33];

    const int t  = threadIdx.x;
    const int p  = blockIdx.y;
    const int q0 = blockIdx.x * 32;

    if (t < 96) {
        l2is[t] = l2i[t];
        int qi = t & 31, d = t >> 5;
        int q = q0 + qi;
        refc[(d << 5) + qi] = (q < GQ) ? ref[(p * GQ + q) * 3 + d] : 0.f;
    }
    __syncthreads();

    if (t < 192) {
        int qi = t & 31, cam = t >> 5;
        float rx = refc[qi], ry = refc[32 + qi], rz = refc[64 + qi];
        float px = fmaf(rx, 100.f, -50.f);
        float py = fmaf(ry, 100.f, -50.f);
        float pz = fmaf(rz,   8.f,  -4.f);
        const float* M = &l2is[cam * 16];
        float cx = fmaf(M[0], px, fmaf(M[1],  py, fmaf(M[2],  pz, M[3])));
        float cy = fmaf(M[4], px, fmaf(M[5],  py, fmaf(M[6],  pz, M[7])));
        float cz = fmaf(M[8], px, fmaf(M[9],  py, fmaf(M[10], pz, M[11])));
        float zs = fmaxf(cz, 1e-6f);
        float u = __fdiv_rn(__fdiv_rn(cx, zs), 704.f);
        float v = __fdiv_rn(__fdiv_rn(cy, zs), 256.f);
        um[cam * 32 + qi] = u;
        vm[cam * 32 + qi] = v;
        vld[cam * 32 + qi] = (cz > 1e-6f) & (u > 0.f) & (u < 1.f)
                           & (v > 0.f) & (v < 1.f);
    }
    __syncthreads();

    const int c    = t & 127;
    const int half = t >> 7;

    for (int it = 0; it < 16; ++it) {
        int qi = it * 2 + half;
        float acc = 0.f;
        #pragma unroll
        for (int cam = 0; cam < NUM_CAMS; ++cam) {
            if (!vld[cam * 32 + qi]) continue;
            float u = um[cam * 32 + qi];
            float v = vm[cam * 32 + qi];
            #pragma unroll
            for (int l = 0; l < 4; ++l) {
                const int W = LW_[l], H = LH_[l];
                float x = fmaf(u, (float)W, -0.5f);
                float y = fmaf(v, (float)H, -0.5f);
                float xf = floorf(x), yf = floorf(y);
                float wx = x - xf,   wy = y - yf;
                int x0 = (int)xf, y0 = (int)yf;
                const float* fb = g_feat + LOFF_[l] + cam * (LHW_[l] << 7);
                bool xa = (x0 >= 0)  & (x0 < W);
                bool xb = (x0 >= -1) & (x0 < W - 1);
                bool ya = (y0 >= 0)  & (y0 < H);
                bool yb = (y0 >= -1) & (y0 < H - 1);
                float v00 = 0.f, v01 = 0.f, v10 = 0.f, v11 = 0.f;
                int base = (y0 * W + x0) << 7;
                if (xa & ya) v00 = fb[base + c];
                if (xb & ya) v01 = fb[base + 128 + c];
                if (xa & yb) v10 = fb[base + (W << 7) + c];
                if (xb & yb) v11 = fb[base + (W << 7) + 128 + c];
                float top = fmaf(v01 - v00, wx, v00);
                float bot = fmaf(v11 - v10, wx, v10);
                acc += fmaf(bot - top, wy, top);
            }
        }
        S[c * 33 + qi] = acc * 0.25f;
    }
    __syncthreads();

    for (int e = t; e < EMBED * 32; e += 256) {
        int cc = e >> 5, qi = e & 31;
        int q = q0 + qi;
        if (q < GQ) {
            int oi = (cc * NP + p) * GQ + q;
            out[oi] += S[cc * 33 + qi];
        }
    }
}

// ---------------------------------------------------------------------------
extern "C" void kernel_launch(void* const* d_in, const int* in_sizes, int n_in,
                              void* d_out, int out_size)
{
    const float* f0  = (const float*)d_in[0];
    const float* f1  = (const float*)d_in[1];
    const float* f2  = (const float*)d_in[2];
    const float* f3  = (const float*)d_in[3];
    const float* ref = (const float*)d_in[4];
    const float* l2i = (const float*)d_in[5];
    const float* w1  = (const float*)d_in[6];
    const float* b1  = (const float*)d_in[7];
    const float* w2  = (const float*)d_in[8];
    const float* b2  = (const float*)d_in[9];
    float* out = (float*)d_out;

    k_prep<<<128, 256>>>(w2);
    k_transpose<<<2832, dim3(32, 8)>>>(f0, f1, f2, f3);

    cudaFuncSetAttribute(k_mlp_mma, cudaFuncAttributeMaxDynamicSharedMemorySize,
                         K1_SMEM);
    k_mlp_mma<<<148, 256, K1_SMEM>>>(ref, w1, b1, b2, out);

    dim3 grid((GQ + 31) / 32, NP);
    k_sample<<<grid, 256>>>(ref, l2i, out);
}

// round 8
// speedup vs baseline: 2.3730x; 1.2801x over previous
#include <cuda_runtime.h>
#include <cuda_bf16.h>
#include <cstdint>

// ---------------------------------------------------------------------------
// BEVSampling (sm_100 baseline PTX — no tcgen05 on this target):
//  k_prep:      w2 fp32 -> split bf16 hi/lo, transposed to [n][k] in gmem
//  k_transpose: NCHW -> NHWC features (tiled, coalesced both sides)
//  k_mlp_mma:   pos-MLP as mma.sync bf16 split GEMM -> writes pos into d_out
//  k_sample:    project + precomputed-tap bilinear sample, += into d_out
// ---------------------------------------------------------------------------

#define NUM_CAMS 6
#define EMBED    128
#define NP       8
#define GQ       10000
#define NPTS     80000
#define FEAT_TOTAL 2872320  // 6*128*(2816+704+176+44)

__device__ float g_feat[FEAT_TOTAL];          // ~11.5 MB NHWC scratch
__device__ __nv_bfloat16 g_w2h[256 * 128];    // w2^T hi, [n][k]
__device__ __nv_bfloat16 g_w2l[256 * 128];    // w2^T lo, [n][k]

// ---------------------------------------------------------------------------
// k_prep: split w2 into bf16 hi/lo, store transposed [n][k] (k contiguous).
// ---------------------------------------------------------------------------
__global__ __launch_bounds__(256) void k_prep(const float* __restrict__ w2)
{
    int i = blockIdx.x * 256 + threadIdx.x;   // 32768 elements
    if (i >= 32768) return;
    int n = i >> 8, k = i & 255;
    float v = w2[k * 128 + n];
    __nv_bfloat16 h = __float2bfloat16(v);
    __nv_bfloat16 l = __float2bfloat16(v - __bfloat162float(h));
    g_w2h[n * 256 + k] = h;
    g_w2l[n * 256 + k] = l;
}

// ---------------------------------------------------------------------------
// k_transpose: tiled NCHW -> NHWC. Block (32,8), 32x32 tiles.
// ---------------------------------------------------------------------------
__global__ __launch_bounds__(256) void k_transpose(
    const float* __restrict__ f0, const float* __restrict__ f1,
    const float* __restrict__ f2, const float* __restrict__ f3)
{
    __shared__ float s[32 * 33];
    int bid = blockIdx.x;
    const float* src; int HW, ptiles, loff, tl;
    if (bid < 2112)      { src = f0; HW = 2816; ptiles = 88; loff = 0;       tl = bid; }
    else if (bid < 2640) { src = f1; HW = 704;  ptiles = 22; loff = 2162688; tl = bid - 2112; }
    else if (bid < 2784) { src = f2; HW = 176;  ptiles = 6;  loff = 2703360; tl = bid - 2640; }
    else                 { src = f3; HW = 44;   ptiles = 2;  loff = 2838528; tl = bid - 2784; }

    int per_cam = ptiles * 4;
    int cam = tl / per_cam;
    int r   = tl - cam * per_cam;
    int c0  = (r & 3) * 32;
    int p0  = (r >> 2) * 32;
    int tx = threadIdx.x, ty = threadIdx.y;

    const float* sp = src + (long)cam * 128 * HW;
    #pragma unroll
    for (int j = 0; j < 4; ++j) {
        int cl = ty + j * 8;
        int p  = p0 + tx;
        float v = (p < HW) ? sp[(c0 + cl) * HW + p] : 0.f;
        s[tx * 33 + cl] = v;
    }
    __syncthreads();
    float* dst = g_feat + loff + (long)cam * HW * 128;
    #pragma unroll
    for (int j = 0; j < 4; ++j) {
        int pl = ty + j * 8;
        int p  = p0 + pl;
        if (p < HW) dst[p * 128 + c0 + tx] = s[pl * 33 + tx];
    }
}

// ---------------------------------------------------------------------------
// mma.sync bf16 helper (sm_80+ baseline, valid on sm_100 non-'a')
// ---------------------------------------------------------------------------
__device__ __forceinline__ void mma_bf16(float* d,
    uint32_t a0, uint32_t a1, uint32_t a2, uint32_t a3,
    uint32_t b0, uint32_t b1)
{
    asm volatile(
        "mma.sync.aligned.m16n8k16.row.col.f32.bf16.bf16.f32 "
        "{%0,%1,%2,%3}, {%4,%5,%6,%7}, {%8,%9}, {%0,%1,%2,%3};"
        : "+f"(d[0]), "+f"(d[1]), "+f"(d[2]), "+f"(d[3])
        : "r"(a0), "r"(a1), "r"(a2), "r"(a3), "r"(b0), "r"(b1));
}

// ---------------------------------------------------------------------------
// K1: out[c*80000 + n] = (relu(ref@w1 + b1) @ w2)[n][c] + b2[c]   (unchanged)
// ---------------------------------------------------------------------------
#define K1_TILES 625
#define SA 136
#define SB 264
#define SM_B2   0
#define SM_B1   512
#define SM_W1   1536
#define SM_REF  4608
#define SM_A    6144
#define SM_AL   40960
#define SM_B    75776
#define SM_BL   143360
#define K1_SMEM 210944

__global__ __launch_bounds__(256) void k_mlp_mma(
    const float* __restrict__ ref,   // [80000, 3]
    const float* __restrict__ w1,    // [3,256]
    const float* __restrict__ b1,    // [256]
    const float* __restrict__ b2,    // [128]
    float* __restrict__ out)         // [128, 80000]
{
    extern __shared__ char smb[];
    float* b2s  = (float*)(smb + SM_B2);
    float* b1s  = (float*)(smb + SM_B1);
    float* w1s  = (float*)(smb + SM_W1);
    float* refs = (float*)(smb + SM_REF);
    __nv_bfloat16* Ah = (__nv_bfloat16*)(smb + SM_A);
    __nv_bfloat16* Al = (__nv_bfloat16*)(smb + SM_AL);
    __nv_bfloat16* Bh = (__nv_bfloat16*)(smb + SM_B);
    __nv_bfloat16* Bl = (__nv_bfloat16*)(smb + SM_BL);
    float* S = (float*)(smb + SM_A);  // epilogue alias [c][132]

    const int t    = threadIdx.x;
    const int wid  = t >> 5;
    const int lane = t & 31;
    const int mw   = wid >> 1;
    const int nw   = (wid & 1) * 64;

    for (int i = t; i < 768; i += 256) w1s[i] = w1[i];
    if (t < 256) b1s[t] = b1[t];
    if (t < 128) b2s[t] = b2[t];
    for (int i = t; i < 128 * 32; i += 256) {
        int n = i >> 5, j = i & 31;
        const uint4* sh = (const uint4*)(g_w2h + n * 256);
        const uint4* sl = (const uint4*)(g_w2l + n * 256);
        *(uint4*)(Bh + n * SB + j * 8) = sh[j];
        *(uint4*)(Bl + n * SB + j * 8) = sl[j];
    }

    for (int tile = blockIdx.x; tile < K1_TILES; tile += 148) {
        const int n0 = tile * 128;

        __syncthreads();
        for (int i = t; i < 384; i += 256) {
            int d = i >> 7, r = i & 127;
            refs[d * 128 + r] = ref[(n0 + r) * 3 + d];
        }

        float acc[2][8][4];
        #pragma unroll
        for (int mt = 0; mt < 2; ++mt)
            #pragma unroll
            for (int nt = 0; nt < 8; ++nt)
                #pragma unroll
                for (int j = 0; j < 4; ++j) acc[mt][nt][j] = 0.f;

        for (int chunk = 0; chunk < 2; ++chunk) {
            const int kb = chunk * 128;
            __syncthreads();

            for (int i = t; i < 128 * 64; i += 256) {
                int row = i >> 6, kp = i & 63;
                int k = kb + kp * 2;
                float x = refs[row], y = refs[128 + row], z = refs[256 + row];
                float h0 = fmaxf(fmaf(x, w1s[k],
                                 fmaf(y, w1s[256 + k],
                                 fmaf(z, w1s[512 + k], b1s[k]))), 0.f);
                float h1 = fmaxf(fmaf(x, w1s[k + 1],
                                 fmaf(y, w1s[256 + k + 1],
                                 fmaf(z, w1s[512 + k + 1], b1s[k + 1]))), 0.f);
                __nv_bfloat16 a0 = __float2bfloat16(h0);
                __nv_bfloat16 a1 = __float2bfloat16(h1);
                __nv_bfloat16 e0 = __float2bfloat16(h0 - __bfloat162float(a0));
                __nv_bfloat16 e1 = __float2bfloat16(h1 - __bfloat162float(a1));
                int idx = row * SA + kp * 2;
                *(__nv_bfloat162*)(Ah + idx) = __halves2bfloat162(a0, a1);
                *(__nv_bfloat162*)(Al + idx) = __halves2bfloat162(e0, e1);
            }
            __syncthreads();

            #pragma unroll
            for (int ks = 0; ks < 8; ++ks) {
                const int k0 = ks * 16;
                const int kg = kb + k0;
                uint32_t ah[2][4], al[2][4];
                #pragma unroll
                for (int mt = 0; mt < 2; ++mt) {
                    int rbase = (mw * 32 + mt * 16 + (lane >> 2)) * SA
                              + k0 + (lane & 3) * 2;
                    ah[mt][0] = *(const uint32_t*)(Ah + rbase);
                    ah[mt][1] = *(const uint32_t*)(Ah + rbase + 8 * SA);
                    ah[mt][2] = *(const uint32_t*)(Ah + rbase + 8);
                    ah[mt][3] = *(const uint32_t*)(Ah + rbase + 8 * SA + 8);
                    al[mt][0] = *(const uint32_t*)(Al + rbase);
                    al[mt][1] = *(const uint32_t*)(Al + rbase + 8 * SA);
                    al[mt][2] = *(const uint32_t*)(Al + rbase + 8);
                    al[mt][3] = *(const uint32_t*)(Al + rbase + 8 * SA + 8);
                }
                #pragma unroll
                for (int nt = 0; nt < 8; ++nt) {
                    int bbase = (nw + nt * 8 + (lane >> 2)) * SB
                              + kg + (lane & 3) * 2;
                    uint32_t bh0 = *(const uint32_t*)(Bh + bbase);
                    uint32_t bh1 = *(const uint32_t*)(Bh + bbase + 8);
                    uint32_t bl0 = *(const uint32_t*)(Bl + bbase);
                    uint32_t bl1 = *(const uint32_t*)(Bl + bbase + 8);
                    #pragma unroll
                    for (int mt = 0; mt < 2; ++mt) {
                        mma_bf16(acc[mt][nt], ah[mt][0], ah[mt][1], ah[mt][2], ah[mt][3], bh0, bh1);
                        mma_bf16(acc[mt][nt], al[mt][0], al[mt][1], al[mt][2], al[mt][3], bh0, bh1);
                        mma_bf16(acc[mt][nt], ah[mt][0], ah[mt][1], ah[mt][2], ah[mt][3], bl0, bl1);
                    }
                }
            }
        }
        __syncthreads();

        #pragma unroll
        for (int mt = 0; mt < 2; ++mt) {
            #pragma unroll
            for (int nt = 0; nt < 8; ++nt) {
                int r = mw * 32 + mt * 16 + (lane >> 2);
                int c = nw + nt * 8 + (lane & 3) * 2;
                S[c * 132 + r]           = acc[mt][nt][0];
                S[(c + 1) * 132 + r]     = acc[mt][nt][1];
                S[c * 132 + r + 8]       = acc[mt][nt][2];
                S[(c + 1) * 132 + r + 8] = acc[mt][nt][3];
            }
        }
        __syncthreads();
        for (int i = t; i < 128 * 128; i += 256) {
            int c = i >> 7, m = i & 127;
            out[c * NPTS + n0 + m] = S[c * 132 + m] + b2s[c];
        }
    }
}

// ---------------------------------------------------------------------------
// K2: projection + bilinear sampling with precomputed tap tables.
// Phase 1: per (cam,qi) project -> u,v,valid.
// Phase 2: deterministic compaction: per (qi, valid cam in ascending order),
//          4 level entries = {4 clamped tap offsets, 4 masked weights*0.25}.
// Phase 3: 4 groups x 64 threads; each thread owns 2 channels (float2).
//          Inner loop per entry: 2 LDS.128 (broadcast) + 4 LDG.64 + 8 FMA.
// ---------------------------------------------------------------------------
__global__ __launch_bounds__(256) void k_sample(
    const float* __restrict__ ref,   // [8, 10000, 3] normalized
    const float* __restrict__ l2i,   // [6,4,4]
    float* __restrict__ out)         // [128, 8, 10000]
{
    __shared__ float  refc[96];
    __shared__ float  l2is[96];
    __shared__ float  um[NUM_CAMS * 32];
    __shared__ float  vm[NUM_CAMS * 32];
    __shared__ int    vld[NUM_CAMS * 32];
    __shared__ int    cnt[32];
    __shared__ int4   entO[32 * 24];
    __shared__ float4 entW[32 * 24];
    __shared__ float  S[EMBED * 33];

    const int t  = threadIdx.x;
    const int p  = blockIdx.y;
    const int q0 = blockIdx.x * 32;

    if (t < 96) {
        l2is[t] = l2i[t];
        int qi = t & 31, d = t >> 5;
        int q = q0 + qi;
        refc[(d << 5) + qi] = (q < GQ) ? ref[(p * GQ + q) * 3 + d] : 0.f;
    }
    __syncthreads();

    // phase 1: project
    if (t < 192) {
        int qi = t & 31, cam = t >> 5;
        float rx = refc[qi], ry = refc[32 + qi], rz = refc[64 + qi];
        float px = fmaf(rx, 100.f, -50.f);
        float py = fmaf(ry, 100.f, -50.f);
        float pz = fmaf(rz,   8.f,  -4.f);
        const float* M = &l2is[cam * 16];
        float cx = fmaf(M[0], px, fmaf(M[1],  py, fmaf(M[2],  pz, M[3])));
        float cy = fmaf(M[4], px, fmaf(M[5],  py, fmaf(M[6],  pz, M[7])));
        float cz = fmaf(M[8], px, fmaf(M[9],  py, fmaf(M[10], pz, M[11])));
        float zs = fmaxf(cz, 1e-6f);
        float u = __fdiv_rn(__fdiv_rn(cx, zs), 704.f);
        float v = __fdiv_rn(__fdiv_rn(cy, zs), 256.f);
        um[cam * 32 + qi] = u;
        vm[cam * 32 + qi] = v;
        vld[cam * 32 + qi] = (cz > 1e-6f) & (u > 0.f) & (u < 1.f)
                           & (v > 0.f) & (v < 1.f);
    }
    __syncthreads();

    // phase 2: deterministic compaction + tap tables
    if (t < 192) {
        int qi = t & 31, cam = t >> 5;
        if (vld[cam * 32 + qi]) {
            int rank = 0;
            for (int pc = 0; pc < cam; ++pc) rank += vld[pc * 32 + qi];
            float u = um[cam * 32 + qi];
            float v = vm[cam * 32 + qi];
            const int LW_[4]   = {88, 44, 22, 11};
            const int LH_[4]   = {32, 16, 8, 4};
            const int LHW_[4]  = {2816, 704, 176, 44};
            const int LOFF_[4] = {0, 2162688, 2703360, 2838528};
            #pragma unroll
            for (int l = 0; l < 4; ++l) {
                const int W = LW_[l], H = LH_[l];
                float x = fmaf(u, (float)W, -0.5f);
                float y = fmaf(v, (float)H, -0.5f);
                float xf = floorf(x), yf = floorf(y);
                float wx = x - xf,   wy = y - yf;
                int x0 = (int)xf, y0 = (int)yf;
                int xc0 = min(max(x0, 0), W - 1);
                int xc1 = min(max(x0 + 1, 0), W - 1);
                int yc0 = min(max(y0, 0), H - 1);
                int yc1 = min(max(y0 + 1, 0), H - 1);
                float okx0 = (x0 >= 0  && x0 < W)     ? 1.f : 0.f;
                float okx1 = (x0 >= -1 && x0 < W - 1) ? 1.f : 0.f;
                float oky0 = (y0 >= 0  && y0 < H)     ? 1.f : 0.f;
                float oky1 = (y0 >= -1 && y0 < H - 1) ? 1.f : 0.f;
                int base = LOFF_[l] + cam * (LHW_[l] << 7);
                int4 O;
                O.x = base + ((yc0 * W + xc0) << 7);
                O.y = base + ((yc0 * W + xc1) << 7);
                O.z = base + ((yc1 * W + xc0) << 7);
                O.w = base + ((yc1 * W + xc1) << 7);
                float4 Wt;
                Wt.x = (1.f - wx) * (1.f - wy) * okx0 * oky0 * 0.25f;
                Wt.y = wx         * (1.f - wy) * okx1 * oky0 * 0.25f;
                Wt.z = (1.f - wx) * wy         * okx0 * oky1 * 0.25f;
                Wt.w = wx         * wy         * okx1 * oky1 * 0.25f;
                int slot = qi * 24 + rank * 4 + l;
                entO[slot] = O;
                entW[slot] = Wt;
            }
        }
    }
    if (t < 32) {
        int s = 0;
        #pragma unroll
        for (int pc = 0; pc < NUM_CAMS; ++pc) s += vld[pc * 32 + t];
        cnt[t] = s * 4;
    }
    __syncthreads();

    // phase 3: channel gather. 4 groups of 64 threads, 2 channels/thread.
    const int tg  = t >> 6;
    const int l64 = t & 63;
    const int c0  = l64 * 2;

    for (int qi = tg; qi < 32; qi += 4) {
        const int n = cnt[qi];
        float ax = 0.f, ay = 0.f;
        for (int e = 0; e < n; ++e) {
            int4   O  = entO[qi * 24 + e];
            float4 Wt = entW[qi * 24 + e];
            float2 v00 = *(const float2*)(g_feat + O.x + c0);
            float2 v01 = *(const float2*)(g_feat + O.y + c0);
            float2 v10 = *(const float2*)(g_feat + O.z + c0);
            float2 v11 = *(const float2*)(g_feat + O.w + c0);
            ax = fmaf(Wt.x, v00.x, fmaf(Wt.y, v01.x,
                 fmaf(Wt.z, v10.x, fmaf(Wt.w, v11.x, ax))));
            ay = fmaf(Wt.x, v00.y, fmaf(Wt.y, v01.y,
                 fmaf(Wt.z, v10.y, fmaf(Wt.w, v11.y, ay))));
        }
        S[c0 * 33 + qi]       = ax;
        S[(c0 + 1) * 33 + qi] = ay;
    }
    __syncthreads();

    // coalesced RMW: out += sampled (pos written by k_mlp_mma)
    for (int e = t; e < EMBED * 32; e += 256) {
        int cc = e >> 5, qi = e & 31;
        int q = q0 + qi;
        if (q < GQ) {
            int oi = (cc * NP + p) * GQ + q;
            out[oi] += S[cc * 33 + qi];
        }
    }
}

// ---------------------------------------------------------------------------
extern "C" void kernel_launch(void* const* d_in, const int* in_sizes, int n_in,
                              void* d_out, int out_size)
{
    const float* f0  = (const float*)d_in[0];
    const float* f1  = (const float*)d_in[1];
    const float* f2  = (const float*)d_in[2];
    const float* f3  = (const float*)d_in[3];
    const float* ref = (const float*)d_in[4];
    const float* l2i = (const float*)d_in[5];
    const float* w1  = (const float*)d_in[6];
    const float* b1  = (const float*)d_in[7];
    const float* w2  = (const float*)d_in[8];
    const float* b2  = (const float*)d_in[9];
    float* out = (float*)d_out;

    k_prep<<<128, 256>>>(w2);
    k_transpose<<<2832, dim3(32, 8)>>>(f0, f1, f2, f3);

    cudaFuncSetAttribute(k_mlp_mma, cudaFuncAttributeMaxDynamicSharedMemorySize,
                         K1_SMEM);
    k_mlp_mma<<<148, 256, K1_SMEM>>>(ref, w1, b1, b2, out);

    dim3 grid((GQ + 31) / 32, NP);
    k_sample<<<grid, 256>>>(ref, l2i, out);
}